// round 1
// baseline (speedup 1.0000x reference)
#include <cuda_runtime.h>

#define E_TOT   300000
#define D_NODE  128
#define D_IN    384
#define D_HID   256
#define D_OUT   128

#define TILE_E   64
#define NTHREADS 256
#define KC1      32
#define KC2      64

// smem: Xs[64*384] + Hs[64*256] + Wp[8192]  = 49152 floats = 192 KB
#define SMEM_FLOATS (TILE_E * D_IN + TILE_E * D_HID + KC1 * D_HID)

typedef unsigned long long u64;

__device__ __forceinline__ u64 ffma2(u64 a, u64 b, u64 c) {
    u64 d;
    asm("fma.rn.f32x2 %0, %1, %2, %3;" : "=l"(d) : "l"(a), "l"(b), "l"(c));
    return d;
}
__device__ __forceinline__ u64 pack2(float lo, float hi) {
    u64 d;
    asm("mov.b64 %0, {%1, %2};" : "=l"(d) : "f"(lo), "f"(hi));
    return d;
}
__device__ __forceinline__ void unpack2(u64 v, float& lo, float& hi) {
    asm("mov.b64 {%0, %1}, %2;" : "=f"(lo), "=f"(hi) : "l"(v));
}

__global__ __launch_bounds__(NTHREADS, 1)
void edge_mlp_kernel(const float* __restrict__ node_attr,
                     const float* __restrict__ edge_attr,
                     const int*   __restrict__ eidx,
                     const float* __restrict__ W1,
                     const float* __restrict__ b1,
                     const float* __restrict__ W2,
                     const float* __restrict__ b2,
                     const float* __restrict__ gamma,
                     const float* __restrict__ beta,
                     float* __restrict__ out)
{
    extern __shared__ float smem[];
    float* Xs = smem;                           // [64][384]
    float* Hs = smem + TILE_E * D_IN;           // [64][256]
    float* Wp = Hs + TILE_E * D_HID;            // [8192] panel

    const int tid  = threadIdx.x;
    const int warp = tid >> 5;   // 0..7 -> owns rows warp*8 .. warp*8+7
    const int lane = tid & 31;
    const int e0   = blockIdx.x * TILE_E;

    // ---------------- Phase 1: gather + concat into Xs ----------------
    {
        const float4* node4 = (const float4*)node_attr;
        const float4* edge4 = (const float4*)edge_attr;
        #pragma unroll
        for (int i = 0; i < 8; i++) {
            int r = warp * 8 + i;
            int e = e0 + r;
            float4 v0 = make_float4(0.f, 0.f, 0.f, 0.f), v1 = v0, v2 = v0;
            if (e < E_TOT) {
                int s = eidx[e];           // senders row
                int t = eidx[E_TOT + e];   // receivers row
                v0 = node4[(size_t)s * 32 + lane];
                v1 = node4[(size_t)t * 32 + lane];
                v2 = edge4[(size_t)e * 32 + lane];
            }
            float4* xrow = (float4*)(Xs + r * D_IN);
            xrow[lane]      = v0;
            xrow[32 + lane] = v1;
            xrow[64 + lane] = v2;
        }
    }
    __syncthreads();

    // ---------------- Phase 2: H = relu(X @ W1 + b1) ----------------
    // thread covers rows warp*8..+8, col pairs (2*lane + 64*j, +1), j=0..3
    u64 acc[8][4];
    {
        #pragma unroll
        for (int j = 0; j < 4; j++) {
            float2 bb = ((const float2*)b1)[lane + 32 * j];
            u64 bi = pack2(bb.x, bb.y);
            #pragma unroll
            for (int i = 0; i < 8; i++) acc[i][j] = bi;
        }
    }
    for (int kb = 0; kb < D_IN; kb += KC1) {
        // stage W1 panel [KC1][256] (contiguous in gmem)
        const float4* src = (const float4*)(W1 + kb * D_HID);
        float4* dst = (float4*)Wp;
        #pragma unroll
        for (int t = 0; t < (KC1 * D_HID / 4) / NTHREADS; t++)
            dst[t * NTHREADS + tid] = src[t * NTHREADS + tid];
        __syncthreads();
        #pragma unroll 8
        for (int k = 0; k < KC1; k++) {
            u64 w[4];
            const float2* wr = (const float2*)(Wp + k * D_HID);
            #pragma unroll
            for (int j = 0; j < 4; j++) {
                float2 f = wr[lane + 32 * j];
                w[j] = pack2(f.x, f.y);
            }
            #pragma unroll
            for (int i = 0; i < 8; i++) {
                float x = Xs[(warp * 8 + i) * D_IN + kb + k];  // warp broadcast
                u64 xd = pack2(x, x);
                #pragma unroll
                for (int j = 0; j < 4; j++)
                    acc[i][j] = ffma2(w[j], xd, acc[i][j]);
            }
        }
        __syncthreads();
    }
    // relu + write Hs
    #pragma unroll
    for (int i = 0; i < 8; i++) {
        int r = warp * 8 + i;
        #pragma unroll
        for (int j = 0; j < 4; j++) {
            float lo, hi;
            unpack2(acc[i][j], lo, hi);
            lo = fmaxf(lo, 0.f);
            hi = fmaxf(hi, 0.f);
            ((float2*)(Hs + r * D_HID))[lane + 32 * j] = make_float2(lo, hi);
        }
    }
    __syncthreads();

    // ---------------- Phase 3: O = H @ W2 + b2 ----------------
    // col pairs (2*lane + 64*j, +1), j=0..1
    u64 acc2[8][2];
    {
        #pragma unroll
        for (int j = 0; j < 2; j++) {
            float2 bb = ((const float2*)b2)[lane + 32 * j];
            u64 bi = pack2(bb.x, bb.y);
            #pragma unroll
            for (int i = 0; i < 8; i++) acc2[i][j] = bi;
        }
    }
    for (int kb = 0; kb < D_HID; kb += KC2) {
        const float4* src = (const float4*)(W2 + kb * D_OUT);
        float4* dst = (float4*)Wp;
        #pragma unroll
        for (int t = 0; t < (KC2 * D_OUT / 4) / NTHREADS; t++)
            dst[t * NTHREADS + tid] = src[t * NTHREADS + tid];
        __syncthreads();
        #pragma unroll 8
        for (int k = 0; k < KC2; k++) {
            u64 w[2];
            const float2* wr = (const float2*)(Wp + k * D_OUT);
            #pragma unroll
            for (int j = 0; j < 2; j++) {
                float2 f = wr[lane + 32 * j];
                w[j] = pack2(f.x, f.y);
            }
            #pragma unroll
            for (int i = 0; i < 8; i++) {
                float x = Hs[(warp * 8 + i) * D_HID + kb + k];  // warp broadcast
                u64 xd = pack2(x, x);
                #pragma unroll
                for (int j = 0; j < 2; j++)
                    acc2[i][j] = ffma2(w[j], xd, acc2[i][j]);
            }
        }
        __syncthreads();
    }

    // ---------------- Phase 4: LayerNorm + store ----------------
    // warp `warp` holds rows warp*8..+8 entirely: 32 lanes x 4 cols = 128
    const float2* g2  = (const float2*)gamma;
    const float2* bt2 = (const float2*)beta;
    #pragma unroll
    for (int i = 0; i < 8; i++) {
        int r = warp * 8 + i;
        int e = e0 + r;
        float v0, v1, v2, v3;
        unpack2(acc2[i][0], v0, v1);
        unpack2(acc2[i][1], v2, v3);
        float s = v0 + v1 + v2 + v3;
        float q = v0 * v0 + v1 * v1 + v2 * v2 + v3 * v3;
        #pragma unroll
        for (int o = 16; o > 0; o >>= 1) {
            s += __shfl_xor_sync(0xffffffffu, s, o);
            q += __shfl_xor_sync(0xffffffffu, q, o);
        }
        float mean = s * (1.0f / 128.0f);
        float var  = q * (1.0f / 128.0f) - mean * mean;
        float inv  = rsqrtf(var + 1e-5f);
        if (e < E_TOT) {
            float2* orow = (float2*)(out + (size_t)e * D_OUT);
            float2 ga = g2[lane];
            float2 bb = bt2[lane];
            orow[lane] = make_float2((v0 - mean) * inv * ga.x + bb.x,
                                     (v1 - mean) * inv * ga.y + bb.y);
            ga = g2[lane + 32];
            bb = bt2[lane + 32];
            orow[lane + 32] = make_float2((v2 - mean) * inv * ga.x + bb.x,
                                          (v3 - mean) * inv * ga.y + bb.y);
        }
    }
}

extern "C" void kernel_launch(void* const* d_in, const int* in_sizes, int n_in,
                              void* d_out, int out_size)
{
    (void)in_sizes; (void)n_in; (void)out_size;
    cudaFuncSetAttribute(edge_mlp_kernel,
                         cudaFuncAttributeMaxDynamicSharedMemorySize,
                         SMEM_FLOATS * (int)sizeof(float));
    dim3 grid((E_TOT + TILE_E - 1) / TILE_E);
    edge_mlp_kernel<<<grid, NTHREADS, SMEM_FLOATS * sizeof(float)>>>(
        (const float*)d_in[0],   // node_attr
        (const float*)d_in[1],   // edge_contact_attr
        (const int*)  d_in[2],   // edge_contact_index
        (const float*)d_in[3],   // W1
        (const float*)d_in[4],   // b1
        (const float*)d_in[5],   // W2
        (const float*)d_in[6],   // b2
        (const float*)d_in[7],   // ln_gamma
        (const float*)d_in[8],   // ln_beta
        (float*)d_out);
}

// round 3
// speedup vs baseline: 2.8458x; 2.8458x over previous
#include <cuda_runtime.h>
#include <cstdint>

#define E_TOT  300000
#define TILE_M 128
#define NTH    512

// ---- smem layout (float offsets) ----
#define OF_B1   0                     // 256
#define OF_B2   256                   // 128
#define OF_G    384                   // 128
#define OF_BT   512                   // 128
#define OF_IS   640                   // 128 sender idx
#define OF_IR   768                   // 128 receiver idx
#define OF_X    896                   // 128*36
#define OF_W    (OF_X + 128*36)       // 32*264 (also holds W2 panel 32*136)
#define OF_H    (OF_W + 32*264)       // 128*260 (also LN scratch 128*132)
#define SMEM_FLOATS (OF_H + 128*260) // 47232 floats = 184.5 KB

#define XS 36    // X chunk row stride
#define W1S 264  // W1 panel row stride
#define W2S 136  // W2 panel row stride
#define HS 260   // H row stride
#define OS 132   // LN scratch row stride

__device__ __forceinline__ uint32_t f2tf(float x) {
    uint32_t r; asm("cvt.rna.tf32.f32 %0, %1;" : "=r"(r) : "f"(x)); return r;
}

__device__ __forceinline__ void mma8(float (&d)[4], const uint32_t (&a)[4],
                                     uint32_t b0, uint32_t b1) {
    asm volatile("mma.sync.aligned.m16n8k8.row.col.f32.tf32.tf32.f32 "
        "{%0,%1,%2,%3}, {%4,%5,%6,%7}, {%8,%9}, {%0,%1,%2,%3};"
        : "+f"(d[0]), "+f"(d[1]), "+f"(d[2]), "+f"(d[3])
        : "r"(a[0]), "r"(a[1]), "r"(a[2]), "r"(a[3]), "r"(b0), "r"(b1));
}

// ---------------- staging helpers ----------------
// X chunk c (0..11): gather -> [128 rows][32 k] (stride 36). 2 float4 per thread.
__device__ __forceinline__ void ldX(int c, int tid, int e0,
                                    const float* __restrict__ node,
                                    const float* __restrict__ edge,
                                    const int* isv, const int* irv, float4 v[2]) {
    #pragma unroll
    for (int it = 0; it < 2; it++) {
        int task = it * NTH + tid;
        int r = task >> 3, q = task & 7;
        const float* src;
        if (c < 4)      src = node + (size_t)isv[r] * 128 + c * 32 + q * 4;
        else if (c < 8) src = node + (size_t)irv[r] * 128 + (c - 4) * 32 + q * 4;
        else {
            int e = e0 + r; if (e >= E_TOT) e = e0;
            src = edge + (size_t)e * 128 + (c - 8) * 32 + q * 4;
        }
        v[it] = *(const float4*)src;
    }
}
__device__ __forceinline__ void stX(int tid, float* smf, const float4 v[2]) {
    #pragma unroll
    for (int it = 0; it < 2; it++) {
        int task = it * NTH + tid;
        int r = task >> 3, q = task & 7;
        uint32_t* d = (uint32_t*)(smf + OF_X + r * XS + q * 4);
        d[0] = f2tf(v[it].x); d[1] = f2tf(v[it].y);
        d[2] = f2tf(v[it].z); d[3] = f2tf(v[it].w);
    }
}
// W1 chunk c (0..11): [32 k][256 n] (stride 264). 4 float4 per thread.
__device__ __forceinline__ void ldW1(int c, int tid, const float* __restrict__ W1, float4 v[4]) {
    #pragma unroll
    for (int it = 0; it < 4; it++) {
        int task = it * NTH + tid;
        int n4 = task & 63, k = task >> 6;
        v[it] = *(const float4*)(W1 + (size_t)(32 * c + k) * 256 + 4 * n4);
    }
}
__device__ __forceinline__ void stW1(int tid, float* smf, const float4 v[4]) {
    #pragma unroll
    for (int it = 0; it < 4; it++) {
        int task = it * NTH + tid;
        int n4 = task & 63, k = task >> 6;
        uint32_t* d = (uint32_t*)(smf + OF_W + k * W1S + 4 * n4);
        d[0] = f2tf(v[it].x); d[1] = f2tf(v[it].y);
        d[2] = f2tf(v[it].z); d[3] = f2tf(v[it].w);
    }
}
// W2 chunk c (0..7): [32 k][128 n] (stride 136). 2 float4 per thread.
__device__ __forceinline__ void ldW2(int c, int tid, const float* __restrict__ W2, float4 v[2]) {
    #pragma unroll
    for (int it = 0; it < 2; it++) {
        int task = it * NTH + tid;
        int n4 = task & 31, k = task >> 5;
        v[it] = *(const float4*)(W2 + (size_t)(32 * c + k) * 128 + 4 * n4);
    }
}
__device__ __forceinline__ void stW2(int tid, float* smf, const float4 v[2]) {
    #pragma unroll
    for (int it = 0; it < 2; it++) {
        int task = it * NTH + tid;
        int n4 = task & 31, k = task >> 5;
        uint32_t* d = (uint32_t*)(smf + OF_W + k * W2S + 4 * n4);
        d[0] = f2tf(v[it].x); d[1] = f2tf(v[it].y);
        d[2] = f2tf(v[it].z); d[3] = f2tf(v[it].w);
    }
}

// ---------------- kernel ----------------
__global__ __launch_bounds__(NTH, 1)
void edge_mlp_mma(const float* __restrict__ node_attr,
                  const float* __restrict__ edge_attr,
                  const int*   __restrict__ eidx,
                  const float* __restrict__ W1,
                  const float* __restrict__ b1,
                  const float* __restrict__ W2,
                  const float* __restrict__ b2,
                  const float* __restrict__ gamma,
                  const float* __restrict__ beta,
                  float* __restrict__ out)
{
    extern __shared__ float smf[];
    const int tid = threadIdx.x;
    const int wid = tid >> 5, lane = tid & 31;
    const int lr = lane >> 2, lc = lane & 3;
    const int e0 = blockIdx.x * TILE_M;

    // constants + indices
    if (tid < 256) smf[OF_B1 + tid] = b1[tid];
    if (tid < 128) {
        smf[OF_B2 + tid] = b2[tid];
        smf[OF_G  + tid] = gamma[tid];
        smf[OF_BT + tid] = beta[tid];
        int e = e0 + tid;
        bool ok = e < E_TOT;
        ((int*)smf)[OF_IS + tid] = ok ? eidx[e] : 0;
        ((int*)smf)[OF_IR + tid] = ok ? eidx[E_TOT + e] : 0;
    }
    __syncthreads();
    const int* isv = (const int*)smf + OF_IS;
    const int* irv = (const int*)smf + OF_IR;

    // prologue: stage chunk 0
    {
        float4 x0[2], w0[4];
        ldX(0, tid, e0, node_attr, edge_attr, isv, irv, x0);
        ldW1(0, tid, W1, w0);
        stX(tid, smf, x0);
        stW1(tid, smf, w0);
    }
    __syncthreads();

    // ======== GEMM1: C1[128x256] = X[128x384] @ W1 ========
    const int wm = wid >> 2;       // 0..3, rows wm*32..+32
    const int wn = wid & 3;        // 0..3, cols wn*64..+64
    float acc[2][8][4];
    #pragma unroll
    for (int i = 0; i < 2; i++)
        #pragma unroll
        for (int j = 0; j < 8; j++)
            #pragma unroll
            for (int q = 0; q < 4; q++) acc[i][j][q] = 0.f;

    const uint32_t* Xs = (const uint32_t*)(smf + OF_X);
    const uint32_t* Ws = (const uint32_t*)(smf + OF_W);

    for (int c = 0; c < 12; c++) {
        float4 xp[2], wp[4];
        if (c < 11) {
            ldX(c + 1, tid, e0, node_attr, edge_attr, isv, irv, xp);
            ldW1(c + 1, tid, W1, wp);
        }
        #pragma unroll
        for (int ks = 0; ks < 4; ks++) {
            uint32_t a[2][4];
            #pragma unroll
            for (int i = 0; i < 2; i++) {
                int r0 = (wm * 32 + i * 16 + lr) * XS + ks * 8 + lc;
                a[i][0] = Xs[r0];
                a[i][1] = Xs[r0 + 8 * XS];
                a[i][2] = Xs[r0 + 4];
                a[i][3] = Xs[r0 + 8 * XS + 4];
            }
            #pragma unroll
            for (int j = 0; j < 8; j++) {
                int cb = wn * 64 + j * 8 + lr;
                uint32_t b0 = Ws[(ks * 8 + lc) * W1S + cb];
                uint32_t b1r = Ws[(ks * 8 + lc + 4) * W1S + cb];
                mma8(acc[0][j], a[0], b0, b1r);
                mma8(acc[1][j], a[1], b0, b1r);
            }
        }
        __syncthreads();
        if (c < 11) {
            stX(tid, smf, xp);
            stW1(tid, smf, wp);
            __syncthreads();
        }
    }

    // ======== epilogue 1: H = tf32(relu(C1 + b1)); stage W2 chunk 0 ========
    {
        uint32_t* Hw = (uint32_t*)(smf + OF_H);
        #pragma unroll
        for (int i = 0; i < 2; i++) {
            int r0 = wm * 32 + i * 16 + lr;
            #pragma unroll
            for (int j = 0; j < 8; j++) {
                int col = wn * 64 + j * 8 + 2 * lc;
                float g0 = smf[OF_B1 + col], g1 = smf[OF_B1 + col + 1];
                Hw[r0 * HS + col]           = f2tf(fmaxf(acc[i][j][0] + g0, 0.f));
                Hw[r0 * HS + col + 1]       = f2tf(fmaxf(acc[i][j][1] + g1, 0.f));
                Hw[(r0 + 8) * HS + col]     = f2tf(fmaxf(acc[i][j][2] + g0, 0.f));
                Hw[(r0 + 8) * HS + col + 1] = f2tf(fmaxf(acc[i][j][3] + g1, 0.f));
            }
        }
        float4 w0[2];
        ldW2(0, tid, W2, w0);
        stW2(tid, smf, w0);
    }
    __syncthreads();

    // ======== GEMM2: C2[128x128] = H[128x256] @ W2 ========
    float acc2[2][4][4];
    #pragma unroll
    for (int i = 0; i < 2; i++)
        #pragma unroll
        for (int j = 0; j < 4; j++)
            #pragma unroll
            for (int q = 0; q < 4; q++) acc2[i][j][q] = 0.f;

    const uint32_t* Hs = (const uint32_t*)(smf + OF_H);
    for (int c = 0; c < 8; c++) {
        float4 wp[2];
        if (c < 7) ldW2(c + 1, tid, W2, wp);
        #pragma unroll
        for (int ks = 0; ks < 4; ks++) {
            int kk = c * 32 + ks * 8;
            uint32_t a[2][4];
            #pragma unroll
            for (int i = 0; i < 2; i++) {
                int r0 = (wm * 32 + i * 16 + lr) * HS + kk + lc;
                a[i][0] = Hs[r0];
                a[i][1] = Hs[r0 + 8 * HS];
                a[i][2] = Hs[r0 + 4];
                a[i][3] = Hs[r0 + 8 * HS + 4];
            }
            #pragma unroll
            for (int j = 0; j < 4; j++) {
                int cb = wn * 32 + j * 8 + lr;
                uint32_t b0 = Ws[(ks * 8 + lc) * W2S + cb];
                uint32_t b1r = Ws[(ks * 8 + lc + 4) * W2S + cb];
                mma8(acc2[0][j], a[0], b0, b1r);
                mma8(acc2[1][j], a[1], b0, b1r);
            }
        }
        __syncthreads();
        if (c < 7) {
            stW2(tid, smf, wp);
            __syncthreads();
        }
    }

    // ======== epilogue 2: O' = C2 + b2 -> smem; LayerNorm -> out ========
    {
        float* Ow = smf + OF_H;   // reuse H region, stride OS
        #pragma unroll
        for (int i = 0; i < 2; i++) {
            int r0 = wm * 32 + i * 16 + lr;
            #pragma unroll
            for (int j = 0; j < 4; j++) {
                int col = wn * 32 + j * 8 + 2 * lc;
                float g0 = smf[OF_B2 + col], g1 = smf[OF_B2 + col + 1];
                Ow[r0 * OS + col]           = acc2[i][j][0] + g0;
                Ow[r0 * OS + col + 1]       = acc2[i][j][1] + g1;
                Ow[(r0 + 8) * OS + col]     = acc2[i][j][2] + g0;
                Ow[(r0 + 8) * OS + col + 1] = acc2[i][j][3] + g1;
            }
        }
    }
    __syncthreads();

    {
        const float* Or = smf + OF_H;
        float4 ga = *(const float4*)(smf + OF_G  + 4 * lane);
        float4 bt = *(const float4*)(smf + OF_BT + 4 * lane);
        #pragma unroll
        for (int rr = 0; rr < 8; rr++) {
            int row = wid * 8 + rr;
            int e = e0 + row;
            float4 v = *(const float4*)(Or + row * OS + 4 * lane);
            float s = v.x + v.y + v.z + v.w;
            float q = v.x * v.x + v.y * v.y + v.z * v.z + v.w * v.w;
            #pragma unroll
            for (int o = 16; o > 0; o >>= 1) {
                s += __shfl_xor_sync(0xffffffffu, s, o);
                q += __shfl_xor_sync(0xffffffffu, q, o);
            }
            float mean = s * (1.0f / 128.0f);
            float var  = q * (1.0f / 128.0f) - mean * mean;
            float inv  = rsqrtf(var + 1e-5f);
            if (e < E_TOT) {
                float4 o4;
                o4.x = (v.x - mean) * inv * ga.x + bt.x;
                o4.y = (v.y - mean) * inv * ga.y + bt.y;
                o4.z = (v.z - mean) * inv * ga.z + bt.z;
                o4.w = (v.w - mean) * inv * ga.w + bt.w;
                *(float4*)(out + (size_t)e * 128 + 4 * lane) = o4;
            }
        }
    }
}

extern "C" void kernel_launch(void* const* d_in, const int* in_sizes, int n_in,
                              void* d_out, int out_size)
{
    (void)in_sizes; (void)n_in; (void)out_size;
    cudaFuncSetAttribute(edge_mlp_mma,
                         cudaFuncAttributeMaxDynamicSharedMemorySize,
                         SMEM_FLOATS * (int)sizeof(float));
    dim3 grid((E_TOT + TILE_M - 1) / TILE_M);
    edge_mlp_mma<<<grid, NTH, SMEM_FLOATS * sizeof(float)>>>(
        (const float*)d_in[0],   // node_attr
        (const float*)d_in[1],   // edge_contact_attr
        (const int*)  d_in[2],   // edge_contact_index
        (const float*)d_in[3],   // W1
        (const float*)d_in[4],   // b1
        (const float*)d_in[5],   // W2
        (const float*)d_in[6],   // b2
        (const float*)d_in[7],   // ln_gamma
        (const float*)d_in[8],   // ln_beta
        (float*)d_out);
}

// round 4
// speedup vs baseline: 3.9382x; 1.3839x over previous
#include <cuda_runtime.h>
#include <cuda_fp16.h>
#include <cstdint>

#define E_TOT   300000
#define N_NODES 50000
#define TILE_M  128
#define NTH     512

// persistent fp16 copies (filled by prologue kernels each launch; deterministic)
__device__ __half g_nodeH[(size_t)N_NODES * 128];
__device__ __half g_W1T[256 * 384];   // [n][k]
__device__ __half g_W2T[128 * 256];   // [n][k]

// ---- dynamic smem byte offsets ----
#define OF_B1  0        // 256 f
#define OF_B2  1024     // 128 f
#define OF_G   1536     // 128 f
#define OF_BT  2048     // 128 f
#define OF_IS  2560     // 128 i
#define OF_IR  3072     // 128 i
#define OF_X0  3584     // 128*40 half
#define OF_X1  13824
#define OF_W0  24064    // 256*40 half
#define OF_W1B 44544
#define OF_H   65024    // 128*264 half  (also reused as float scratch 128*132)
#define SMEM_BYTES (OF_H + 128*264*2)   // 132608

#define XS 40    // X chunk row stride (half)
#define WS 40    // W panel row stride (half)
#define HS 264   // H row stride (half)
#define OS 132   // LN scratch row stride (float)

__device__ __forceinline__ uint32_t pkh2(float lo, float hi) {
    uint32_t r; asm("cvt.rn.f16x2.f32 %0, %1, %2;" : "=r"(r) : "f"(hi), "f"(lo)); return r;
}
__device__ __forceinline__ void mma16(float (&d)[4], const uint32_t (&a)[4],
                                      uint32_t b0, uint32_t b1) {
    asm volatile("mma.sync.aligned.m16n8k16.row.col.f32.f16.f16.f32 "
        "{%0,%1,%2,%3}, {%4,%5,%6,%7}, {%8,%9}, {%0,%1,%2,%3};"
        : "+f"(d[0]), "+f"(d[1]), "+f"(d[2]), "+f"(d[3])
        : "r"(a[0]), "r"(a[1]), "r"(a[2]), "r"(a[3]), "r"(b0), "r"(b1));
}

// ---------------- prologue kernels ----------------
__global__ void cvt_node_kernel(const float* __restrict__ node) {
    int n8 = N_NODES * 128 / 8;
    for (int i = blockIdx.x * blockDim.x + threadIdx.x; i < n8; i += gridDim.x * blockDim.x) {
        float4 a = *(const float4*)(node + 8 * (size_t)i);
        float4 b = *(const float4*)(node + 8 * (size_t)i + 4);
        uint4 o;
        o.x = pkh2(a.x, a.y); o.y = pkh2(a.z, a.w);
        o.z = pkh2(b.x, b.y); o.w = pkh2(b.z, b.w);
        *(uint4*)(g_nodeH + 8 * (size_t)i) = o;
    }
}
__global__ void cvt_w_kernel(const float* __restrict__ W1, const float* __restrict__ W2) {
    for (int i = blockIdx.x * blockDim.x + threadIdx.x; i < 384 * 256 + 256 * 128;
         i += gridDim.x * blockDim.x) {
        if (i < 384 * 256) {
            int k = i >> 8, n = i & 255;
            g_W1T[n * 384 + k] = __float2half_rn(W1[i]);
        } else {
            int j = i - 384 * 256;
            int k = j >> 7, n = j & 127;
            g_W2T[n * 256 + k] = __float2half_rn(W2[j]);
        }
    }
}

// ---------------- staging ----------------
// X chunk c (k 32c..32c+32): [128][XS] half. 1 uint4 (8 half) per thread.
__device__ __forceinline__ uint4 ldX(int c, int tid, int e0,
                                     const float* __restrict__ edge,
                                     const int* isv, const int* irv) {
    int r = tid >> 2, q = tid & 3;
    if (c < 8) {
        int row = (c < 4) ? isv[r] : irv[r];
        int cc = (c < 4) ? c : c - 4;
        return *(const uint4*)(g_nodeH + (size_t)row * 128 + cc * 32 + q * 8);
    } else {
        int e = e0 + r; if (e >= E_TOT) e = e0;
        const float* s = edge + (size_t)e * 128 + (c - 8) * 32 + q * 8;
        float4 a = *(const float4*)s, b = *(const float4*)(s + 4);
        uint4 o;
        o.x = pkh2(a.x, a.y); o.y = pkh2(a.z, a.w);
        o.z = pkh2(b.x, b.y); o.w = pkh2(b.z, b.w);
        return o;
    }
}
__device__ __forceinline__ void stX(__half* xb, int tid, uint4 v) {
    int r = tid >> 2, q = tid & 3;
    *(uint4*)(xb + r * XS + q * 8) = v;
}
// W1 chunk c: [256 n][32 k] -> 2 uint4 per thread
__device__ __forceinline__ void ldW1(int c, int tid, uint4 v[2]) {
    int n = tid >> 1, h = tid & 1;
    const __half* s = g_W1T + (size_t)n * 384 + c * 32 + h * 16;
    v[0] = *(const uint4*)s;
    v[1] = *(const uint4*)(s + 8);
}
__device__ __forceinline__ void stW1(__half* wb, int tid, const uint4 v[2]) {
    int n = tid >> 1, h = tid & 1;
    *(uint4*)(wb + n * WS + h * 16)     = v[0];
    *(uint4*)(wb + n * WS + h * 16 + 8) = v[1];
}
// W2 chunk c: [128 n][32 k] -> 1 uint4 per thread
__device__ __forceinline__ uint4 ldW2(int c, int tid) {
    int n = tid >> 2, q = tid & 3;
    return *(const uint4*)(g_W2T + (size_t)n * 256 + c * 32 + q * 8);
}
__device__ __forceinline__ void stW2(__half* wb, int tid, uint4 v) {
    int n = tid >> 2, q = tid & 3;
    *(uint4*)(wb + n * WS + q * 8) = v;
}

// ---------------- main kernel ----------------
__global__ __launch_bounds__(NTH, 1)
void edge_mlp_h(const float* __restrict__ edge_attr,
                const int*   __restrict__ eidx,
                const float* __restrict__ b1,
                const float* __restrict__ b2,
                const float* __restrict__ gamma,
                const float* __restrict__ beta,
                float* __restrict__ out)
{
    extern __shared__ char smem[];
    float* smf = (float*)smem;
    const int tid = threadIdx.x;
    const int wid = tid >> 5, lane = tid & 31;
    const int lr = lane >> 2, lc = lane & 3;
    const int wm = wid >> 2, wn = wid & 3;
    const int e0 = blockIdx.x * TILE_M;

    if (tid < 256) smf[OF_B1 / 4 + tid] = b1[tid];
    if (tid < 128) {
        smf[OF_B2 / 4 + tid] = b2[tid];
        smf[OF_G  / 4 + tid] = gamma[tid];
        smf[OF_BT / 4 + tid] = beta[tid];
        int e = e0 + tid;
        bool ok = e < E_TOT;
        ((int*)(smem + OF_IS))[tid] = ok ? eidx[e] : 0;
        ((int*)(smem + OF_IR))[tid] = ok ? eidx[E_TOT + e] : 0;
    }
    __syncthreads();
    const int* isv = (const int*)(smem + OF_IS);
    const int* irv = (const int*)(smem + OF_IR);
    __half* Xb[2] = { (__half*)(smem + OF_X0), (__half*)(smem + OF_X1) };
    __half* Wb[2] = { (__half*)(smem + OF_W0), (__half*)(smem + OF_W1B) };
    __half* Hh = (__half*)(smem + OF_H);

    // prologue: stage chunk 0 into buf 0
    {
        uint4 xv = ldX(0, tid, e0, edge_attr, isv, irv);
        uint4 wv[2]; ldW1(0, tid, wv);
        stX(Xb[0], tid, xv);
        stW1(Wb[0], tid, wv);
    }
    __syncthreads();

    // ======== GEMM1: C1[128x256] = X[128x384] @ W1 ========
    float acc[2][8][4];
    #pragma unroll
    for (int i = 0; i < 2; i++)
        #pragma unroll
        for (int j = 0; j < 8; j++)
            #pragma unroll
            for (int q = 0; q < 4; q++) acc[i][j][q] = 0.f;

    for (int c = 0; c < 12; c++) {
        uint4 xv; uint4 wv[2];
        if (c < 11) { xv = ldX(c + 1, tid, e0, edge_attr, isv, irv); ldW1(c + 1, tid, wv); }
        const __half* Xs = Xb[c & 1];
        const __half* Ws = Wb[c & 1];
        #pragma unroll
        for (int ks = 0; ks < 2; ks++) {
            uint32_t A[2][4];
            #pragma unroll
            for (int i = 0; i < 2; i++) {
                const __half* p = Xs + (wm * 32 + i * 16 + lr) * XS + ks * 16 + 2 * lc;
                A[i][0] = *(const uint32_t*)p;
                A[i][1] = *(const uint32_t*)(p + 8 * XS);
                A[i][2] = *(const uint32_t*)(p + 8);
                A[i][3] = *(const uint32_t*)(p + 8 * XS + 8);
            }
            #pragma unroll
            for (int j = 0; j < 8; j++) {
                const __half* p = Ws + (wn * 64 + j * 8 + lr) * WS + ks * 16 + 2 * lc;
                uint32_t b0 = *(const uint32_t*)p;
                uint32_t b1r = *(const uint32_t*)(p + 8);
                mma16(acc[0][j], A[0], b0, b1r);
                mma16(acc[1][j], A[1], b0, b1r);
            }
        }
        if (c < 11) { stX(Xb[(c + 1) & 1], tid, xv); stW1(Wb[(c + 1) & 1], tid, wv); }
        __syncthreads();
    }

    // ======== epilogue 1: H = fp16(relu(C1+b1)); stage W2 chunk 0 ========
    {
        uint4 w0 = ldW2(0, tid);
        #pragma unroll
        for (int i = 0; i < 2; i++) {
            int r0 = wm * 32 + i * 16 + lr;
            #pragma unroll
            for (int j = 0; j < 8; j++) {
                int col = wn * 64 + j * 8 + 2 * lc;
                float g0 = smf[OF_B1 / 4 + col], g1 = smf[OF_B1 / 4 + col + 1];
                *(uint32_t*)(Hh + r0 * HS + col) =
                    pkh2(fmaxf(acc[i][j][0] + g0, 0.f), fmaxf(acc[i][j][1] + g1, 0.f));
                *(uint32_t*)(Hh + (r0 + 8) * HS + col) =
                    pkh2(fmaxf(acc[i][j][2] + g0, 0.f), fmaxf(acc[i][j][3] + g1, 0.f));
            }
        }
        stW2(Wb[0], tid, w0);
    }
    __syncthreads();

    // ======== GEMM2: C2[128x128] = H[128x256] @ W2 ========
    float acc2[2][4][4];
    #pragma unroll
    for (int i = 0; i < 2; i++)
        #pragma unroll
        for (int j = 0; j < 4; j++)
            #pragma unroll
            for (int q = 0; q < 4; q++) acc2[i][j][q] = 0.f;

    for (int c = 0; c < 8; c++) {
        uint4 wv;
        if (c < 7) wv = ldW2(c + 1, tid);
        const __half* Ws = Wb[c & 1];
        #pragma unroll
        for (int ks = 0; ks < 2; ks++) {
            int kk = c * 32 + ks * 16;
            uint32_t A[2][4];
            #pragma unroll
            for (int i = 0; i < 2; i++) {
                const __half* p = Hh + (wm * 32 + i * 16 + lr) * HS + kk + 2 * lc;
                A[i][0] = *(const uint32_t*)p;
                A[i][1] = *(const uint32_t*)(p + 8 * HS);
                A[i][2] = *(const uint32_t*)(p + 8);
                A[i][3] = *(const uint32_t*)(p + 8 * HS + 8);
            }
            #pragma unroll
            for (int j = 0; j < 4; j++) {
                const __half* p = Ws + (wn * 32 + j * 8 + lr) * WS + ks * 16 + 2 * lc;
                uint32_t b0 = *(const uint32_t*)p;
                uint32_t b1r = *(const uint32_t*)(p + 8);
                mma16(acc2[0][j], A[0], b0, b1r);
                mma16(acc2[1][j], A[1], b0, b1r);
            }
        }
        if (c < 7) stW2(Wb[(c + 1) & 1], tid, wv);
        __syncthreads();
    }

    // ======== epilogue 2: scratch = C2 + b2 ; LayerNorm -> out ========
    {
        float* Of = (float*)(smem + OF_H);   // reuse H region
        #pragma unroll
        for (int i = 0; i < 2; i++) {
            int r0 = wm * 32 + i * 16 + lr;
            #pragma unroll
            for (int j = 0; j < 4; j++) {
                int col = wn * 32 + j * 8 + 2 * lc;
                float g0 = smf[OF_B2 / 4 + col], g1 = smf[OF_B2 / 4 + col + 1];
                Of[r0 * OS + col]           = acc2[i][j][0] + g0;
                Of[r0 * OS + col + 1]       = acc2[i][j][1] + g1;
                Of[(r0 + 8) * OS + col]     = acc2[i][j][2] + g0;
                Of[(r0 + 8) * OS + col + 1] = acc2[i][j][3] + g1;
            }
        }
    }
    __syncthreads();
    {
        const float* Of = (const float*)(smem + OF_H);
        float4 ga = *(const float4*)(smf + OF_G  / 4 + 4 * lane);
        float4 bt = *(const float4*)(smf + OF_BT / 4 + 4 * lane);
        #pragma unroll
        for (int rr = 0; rr < 8; rr++) {
            int row = wid * 8 + rr;
            int e = e0 + row;
            float4 v = *(const float4*)(Of + row * OS + 4 * lane);
            float s = v.x + v.y + v.z + v.w;
            float q = v.x * v.x + v.y * v.y + v.z * v.z + v.w * v.w;
            #pragma unroll
            for (int o = 16; o > 0; o >>= 1) {
                s += __shfl_xor_sync(0xffffffffu, s, o);
                q += __shfl_xor_sync(0xffffffffu, q, o);
            }
            float mean = s * (1.0f / 128.0f);
            float var  = q * (1.0f / 128.0f) - mean * mean;
            float inv  = rsqrtf(var + 1e-5f);
            if (e < E_TOT) {
                float4 o4;
                o4.x = (v.x - mean) * inv * ga.x + bt.x;
                o4.y = (v.y - mean) * inv * ga.y + bt.y;
                o4.z = (v.z - mean) * inv * ga.z + bt.z;
                o4.w = (v.w - mean) * inv * ga.w + bt.w;
                *(float4*)(out + (size_t)e * 128 + 4 * lane) = o4;
            }
        }
    }
}

extern "C" void kernel_launch(void* const* d_in, const int* in_sizes, int n_in,
                              void* d_out, int out_size)
{
    (void)in_sizes; (void)n_in; (void)out_size;
    cvt_node_kernel<<<2048, 256>>>((const float*)d_in[0]);
    cvt_w_kernel<<<256, 512>>>((const float*)d_in[3], (const float*)d_in[5]);
    cudaFuncSetAttribute(edge_mlp_h,
                         cudaFuncAttributeMaxDynamicSharedMemorySize, SMEM_BYTES);
    dim3 grid((E_TOT + TILE_M - 1) / TILE_M);
    edge_mlp_h<<<grid, NTH, SMEM_BYTES>>>(
        (const float*)d_in[1],   // edge_contact_attr
        (const int*)  d_in[2],   // edge_contact_index
        (const float*)d_in[4],   // b1
        (const float*)d_in[6],   // b2
        (const float*)d_in[7],   // ln_gamma
        (const float*)d_in[8],   // ln_beta
        (float*)d_out);
}

// round 5
// speedup vs baseline: 5.3962x; 1.3702x over previous
#include <cuda_runtime.h>
#include <cuda_fp16.h>
#include <cstdint>

#define E_TOT   300000
#define N_NODES 50000
#define TILE_M  128
#define NTH     512

__device__ __half g_nodeH[(size_t)N_NODES * 128];
__device__ __half g_W1T[256 * 384];   // [n][k]
__device__ __half g_W2T[128 * 256];   // [n][k]

// ---- dynamic smem byte offsets ----
#define OF_B1  0         // 256 f
#define OF_B2  1024      // 128 f
#define OF_G   1536      // 128 f
#define OF_BT  2048      // 128 f
#define OF_X0  2560      // 128*40 half = 10240 B
#define OF_X1  12800
#define OF_W0  23040     // 256*40 half = 20480 B
#define OF_W1B 43520
#define OF_H   64000     // 128*264 half = 67584 B (reused as float scratch 128*132)
#define SMEM_BYTES (OF_H + 128*264*2)   // 131584

#define XS 40    // X chunk row stride (half)
#define WS 40    // W panel row stride (half)
#define HS 264   // H row stride (half)
#define OS 132   // LN scratch row stride (float)

__device__ __forceinline__ uint32_t smem_u32(const void* p) {
    uint32_t a;
    asm("{ .reg .u64 t; cvta.to.shared.u64 t, %1; cvt.u32.u64 %0, t; }" : "=r"(a) : "l"(p));
    return a;
}
__device__ __forceinline__ uint32_t pkh2(float lo, float hi) {
    uint32_t r; asm("cvt.rn.f16x2.f32 %0, %1, %2;" : "=r"(r) : "f"(hi), "f"(lo)); return r;
}
__device__ __forceinline__ void mma16(float (&d)[4], const uint32_t (&a)[4],
                                      uint32_t b0, uint32_t b1) {
    asm volatile("mma.sync.aligned.m16n8k16.row.col.f32.f16.f16.f32 "
        "{%0,%1,%2,%3}, {%4,%5,%6,%7}, {%8,%9}, {%0,%1,%2,%3};"
        : "+f"(d[0]), "+f"(d[1]), "+f"(d[2]), "+f"(d[3])
        : "r"(a[0]), "r"(a[1]), "r"(a[2]), "r"(a[3]), "r"(b0), "r"(b1));
}
__device__ __forceinline__ void ldsm4(uint32_t (&r)[4], uint32_t addr) {
    asm volatile("ldmatrix.sync.aligned.m8n8.x4.shared.b16 {%0,%1,%2,%3}, [%4];"
        : "=r"(r[0]), "=r"(r[1]), "=r"(r[2]), "=r"(r[3]) : "r"(addr));
}
#define CP16(dst, src) asm volatile("cp.async.ca.shared.global [%0], [%1], 16;" :: "r"(dst), "l"(src) : "memory")
#define CP_COMMIT()    asm volatile("cp.async.commit_group;" ::: "memory")
#define CP_WAIT0()     asm volatile("cp.async.wait_group 0;" ::: "memory")

// ---------------- prologue: fp16 conversion + weight transpose ----------------
__global__ void cvt_all_kernel(const float* __restrict__ node,
                               const float* __restrict__ W1,
                               const float* __restrict__ W2) {
    const int NODE8 = N_NODES * 128 / 8;          // 800000 uint4 segs
    const int WTOT  = 384 * 256 + 256 * 128;      // 131072 elems
    for (int i = blockIdx.x * blockDim.x + threadIdx.x; i < NODE8 + WTOT;
         i += gridDim.x * blockDim.x) {
        if (i < NODE8) {
            float4 a = *(const float4*)(node + 8 * (size_t)i);
            float4 b = *(const float4*)(node + 8 * (size_t)i + 4);
            uint4 o;
            o.x = pkh2(a.x, a.y); o.y = pkh2(a.z, a.w);
            o.z = pkh2(b.x, b.y); o.w = pkh2(b.z, b.w);
            *(uint4*)(g_nodeH + 8 * (size_t)i) = o;
        } else {
            int j = i - NODE8;
            if (j < 384 * 256) {
                int k = j >> 8, n = j & 255;
                g_W1T[n * 384 + k] = __float2half_rn(W1[j]);
            } else {
                int m = j - 384 * 256;
                int k = m >> 7, n = m & 127;
                g_W2T[n * 256 + k] = __float2half_rn(W2[m]);
            }
        }
    }
}

// ---------------- main kernel ----------------
__global__ __launch_bounds__(NTH, 1)
void edge_mlp_h(const float* __restrict__ edge_attr,
                const int*   __restrict__ eidx,
                const float* __restrict__ b1,
                const float* __restrict__ b2,
                const float* __restrict__ gamma,
                const float* __restrict__ beta,
                float* __restrict__ out)
{
    extern __shared__ char smem[];
    float* smf = (float*)smem;
    const int tid = threadIdx.x;
    const int wid = tid >> 5, lane = tid & 31;
    const int lr = lane >> 2, lc = lane & 3;
    const int wm = wid >> 2, wn = wid & 3;
    const int e0 = blockIdx.x * TILE_M;

    if (tid < 256) smf[OF_B1 / 4 + tid] = b1[tid];
    if (tid < 128) {
        smf[OF_B2 / 4 + tid] = b2[tid];
        smf[OF_G  / 4 + tid] = gamma[tid];
        smf[OF_BT / 4 + tid] = beta[tid];
    }

    // per-thread staging role: row r = tid>>2 (0..127), seg q = tid&3
    const int r = tid >> 2, q = tid & 3;
    int eMine = e0 + r; if (eMine >= E_TOT) eMine = e0;
    const int sIdx = eidx[eMine];
    const int rIdx = eidx[E_TOT + eMine];
    const __half* pS = g_nodeH + (size_t)sIdx * 128 + q * 8;   // + cc*32
    const __half* pR = g_nodeH + (size_t)rIdx * 128 + q * 8;
    const float*  pE = edge_attr + (size_t)eMine * 128 + q * 8; // + (cc-8)*32
    const __half* pW1 = g_W1T + (size_t)(tid >> 1) * 384 + (tid & 1) * 16; // 2 segs: +0,+8; + c*32
    const __half* pW2 = g_W2T + (size_t)r * 256 + q * 8;                   // + c*32

    const uint32_t sbX[2] = { smem_u32(smem + OF_X0), smem_u32(smem + OF_X1) };
    const uint32_t sbW[2] = { smem_u32(smem + OF_W0), smem_u32(smem + OF_W1B) };
    const uint32_t sbH    = smem_u32(smem + OF_H);
    const uint32_t dX = (uint32_t)(r * XS + q * 8) * 2;
    const uint32_t dW1a = (uint32_t)((tid >> 1) * WS + (tid & 1) * 16) * 2;
    const uint32_t dW2 = (uint32_t)(r * WS + q * 8) * 2;

    // ldmatrix per-thread offsets
    const int aoff_row = lane & 15;
    const int aoff_k   = (lane >> 4) << 3;
    const int boff_n   = ((lane >> 4) << 3) + (lane & 7);
    const int boff_k   = ((lane >> 3) & 1) << 3;

    // prologue: stage chunk 0 (node X + W1) via cp.async
    CP16(sbX[0] + dX, pS);
    CP16(sbW[0] + dW1a,      pW1);
    CP16(sbW[0] + dW1a + 16, pW1 + 8);
    CP_COMMIT(); CP_WAIT0();
    __syncthreads();

    // ======== GEMM1: C1[128x256] = X[128x384] @ W1 ========
    float acc[2][8][4];
    #pragma unroll
    for (int i = 0; i < 2; i++)
        #pragma unroll
        for (int j = 0; j < 8; j++)
            #pragma unroll
            for (int qq = 0; qq < 4; qq++) acc[i][j][qq] = 0.f;

    for (int c = 0; c < 12; c++) {
        const bool pre = c < 11;
        const int cn = c + 1;
        float4 ev0, ev1;
        bool edge_pre = false;
        if (pre) {
            if (cn < 8) {
                const __half* src = (cn < 4) ? (pS + cn * 32) : (pR + (cn - 4) * 32);
                CP16(sbX[cn & 1] + dX, src);
            } else {
                const float* src = pE + (cn - 8) * 32;
                ev0 = *(const float4*)src;
                ev1 = *(const float4*)(src + 4);
                edge_pre = true;
            }
            CP16(sbW[cn & 1] + dW1a,      pW1 + cn * 32);
            CP16(sbW[cn & 1] + dW1a + 16, pW1 + cn * 32 + 8);
            CP_COMMIT();
        }
        const uint32_t xb = sbX[c & 1], wb = sbW[c & 1];
        #pragma unroll
        for (int ks = 0; ks < 2; ks++) {
            uint32_t A[2][4];
            #pragma unroll
            for (int i = 0; i < 2; i++)
                ldsm4(A[i], xb + (uint32_t)((wm * 32 + i * 16 + aoff_row) * XS + ks * 16 + aoff_k) * 2);
            #pragma unroll
            for (int jp = 0; jp < 4; jp++) {
                uint32_t B[4];
                ldsm4(B, wb + (uint32_t)((wn * 64 + jp * 16 + boff_n) * WS + ks * 16 + boff_k) * 2);
                mma16(acc[0][2 * jp],     A[0], B[0], B[1]);
                mma16(acc[1][2 * jp],     A[1], B[0], B[1]);
                mma16(acc[0][2 * jp + 1], A[0], B[2], B[3]);
                mma16(acc[1][2 * jp + 1], A[1], B[2], B[3]);
            }
        }
        if (edge_pre) {
            uint4 o;
            o.x = pkh2(ev0.x, ev0.y); o.y = pkh2(ev0.z, ev0.w);
            o.z = pkh2(ev1.x, ev1.y); o.w = pkh2(ev1.z, ev1.w);
            asm volatile("st.shared.v4.b32 [%0], {%1,%2,%3,%4};"
                :: "r"(sbX[cn & 1] + dX), "r"(o.x), "r"(o.y), "r"(o.z), "r"(o.w) : "memory");
        }
        if (pre) CP_WAIT0();
        __syncthreads();
    }

    // ======== epilogue 1: H = fp16(relu(C1+b1)); cp.async W2 chunk 0 ========
    {
        __half* Hh = (__half*)(smem + OF_H);
        CP16(sbW[0] + dW2, pW2);
        CP_COMMIT();
        #pragma unroll
        for (int i = 0; i < 2; i++) {
            int r0 = wm * 32 + i * 16 + lr;
            #pragma unroll
            for (int j = 0; j < 8; j++) {
                int col = wn * 64 + j * 8 + 2 * lc;
                float g0 = smf[OF_B1 / 4 + col], g1 = smf[OF_B1 / 4 + col + 1];
                *(uint32_t*)(Hh + r0 * HS + col) =
                    pkh2(fmaxf(acc[i][j][0] + g0, 0.f), fmaxf(acc[i][j][1] + g1, 0.f));
                *(uint32_t*)(Hh + (r0 + 8) * HS + col) =
                    pkh2(fmaxf(acc[i][j][2] + g0, 0.f), fmaxf(acc[i][j][3] + g1, 0.f));
            }
        }
        CP_WAIT0();
    }
    __syncthreads();

    // ======== GEMM2: C2[128x128] = H[128x256] @ W2 ========
    float acc2[2][4][4];
    #pragma unroll
    for (int i = 0; i < 2; i++)
        #pragma unroll
        for (int j = 0; j < 4; j++)
            #pragma unroll
            for (int qq = 0; qq < 4; qq++) acc2[i][j][qq] = 0.f;

    for (int c = 0; c < 8; c++) {
        if (c < 7) {
            CP16(sbW[(c + 1) & 1] + dW2, pW2 + (c + 1) * 32);
            CP_COMMIT();
        }
        const uint32_t wb = sbW[c & 1];
        #pragma unroll
        for (int ks = 0; ks < 2; ks++) {
            uint32_t A[2][4];
            #pragma unroll
            for (int i = 0; i < 2; i++)
                ldsm4(A[i], sbH + (uint32_t)((wm * 32 + i * 16 + aoff_row) * HS + c * 32 + ks * 16 + aoff_k) * 2);
            #pragma unroll
            for (int jp = 0; jp < 2; jp++) {
                uint32_t B[4];
                ldsm4(B, wb + (uint32_t)((wn * 32 + jp * 16 + boff_n) * WS + ks * 16 + boff_k) * 2);
                mma16(acc2[0][2 * jp],     A[0], B[0], B[1]);
                mma16(acc2[1][2 * jp],     A[1], B[0], B[1]);
                mma16(acc2[0][2 * jp + 1], A[0], B[2], B[3]);
                mma16(acc2[1][2 * jp + 1], A[1], B[2], B[3]);
            }
        }
        if (c < 7) CP_WAIT0();
        __syncthreads();
    }

    // ======== epilogue 2: scratch = C2 + b2 ; LayerNorm -> out ========
    {
        float* Of = (float*)(smem + OF_H);
        #pragma unroll
        for (int i = 0; i < 2; i++) {
            int r0 = wm * 32 + i * 16 + lr;
            #pragma unroll
            for (int j = 0; j < 4; j++) {
                int col = wn * 32 + j * 8 + 2 * lc;
                float g0 = smf[OF_B2 / 4 + col], g1 = smf[OF_B2 / 4 + col + 1];
                Of[r0 * OS + col]           = acc2[i][j][0] + g0;
                Of[r0 * OS + col + 1]       = acc2[i][j][1] + g1;
                Of[(r0 + 8) * OS + col]     = acc2[i][j][2] + g0;
                Of[(r0 + 8) * OS + col + 1] = acc2[i][j][3] + g1;
            }
        }
    }
    __syncthreads();
    {
        const float* Of = (const float*)(smem + OF_H);
        float4 ga = *(const float4*)(smf + OF_G  / 4 + 4 * lane);
        float4 bt = *(const float4*)(smf + OF_BT / 4 + 4 * lane);
        #pragma unroll
        for (int rr = 0; rr < 8; rr++) {
            int row = wid * 8 + rr;
            int e = e0 + row;
            float4 v = *(const float4*)(Of + row * OS + 4 * lane);
            float s = v.x + v.y + v.z + v.w;
            float qs = v.x * v.x + v.y * v.y + v.z * v.z + v.w * v.w;
            #pragma unroll
            for (int o = 16; o > 0; o >>= 1) {
                s  += __shfl_xor_sync(0xffffffffu, s, o);
                qs += __shfl_xor_sync(0xffffffffu, qs, o);
            }
            float mean = s * (1.0f / 128.0f);
            float var  = qs * (1.0f / 128.0f) - mean * mean;
            float inv  = rsqrtf(var + 1e-5f);
            if (e < E_TOT) {
                float4 o4;
                o4.x = (v.x - mean) * inv * ga.x + bt.x;
                o4.y = (v.y - mean) * inv * ga.y + bt.y;
                o4.z = (v.z - mean) * inv * ga.z + bt.z;
                o4.w = (v.w - mean) * inv * ga.w + bt.w;
                *(float4*)(out + (size_t)e * 128 + 4 * lane) = o4;
            }
        }
    }
}

extern "C" void kernel_launch(void* const* d_in, const int* in_sizes, int n_in,
                              void* d_out, int out_size)
{
    (void)in_sizes; (void)n_in; (void)out_size;
    cvt_all_kernel<<<2048, 256>>>((const float*)d_in[0],
                                  (const float*)d_in[3],
                                  (const float*)d_in[5]);
    cudaFuncSetAttribute(edge_mlp_h,
                         cudaFuncAttributeMaxDynamicSharedMemorySize, SMEM_BYTES);
    dim3 grid((E_TOT + TILE_M - 1) / TILE_M);
    edge_mlp_h<<<grid, NTH, SMEM_BYTES>>>(
        (const float*)d_in[1],   // edge_contact_attr
        (const int*)  d_in[2],   // edge_contact_index
        (const float*)d_in[4],   // b1
        (const float*)d_in[6],   // b2
        (const float*)d_in[7],   // ln_gamma
        (const float*)d_in[8],   // ln_beta
        (float*)d_out);
}